// round 15
// baseline (speedup 1.0000x reference)
#include <cuda_runtime.h>
#include <math.h>
#include <stddef.h>

#define BB 512
#define LL 100
#define EE 256
#define HH 256
#define TT 100

// ---------------- device scratch (no allocations allowed) ----------------
__device__ float d_eg[(size_t)BB * LL * HH];   // [b][l][h]  52.4 MB
__device__ float d_ep[(size_t)BB * LL * HH];   // [b][l][h]  52.4 MB
__device__ float d_wperm[512 * 1024];          // [k][n], n = 4h+g  (2 MB)
__device__ float d_bsum[1024];                 // bi+bh, gate-interleaved

__device__ __forceinline__ float sigf(float x) { return __fdividef(1.f, 1.f + __expf(-x)); }
__device__ __forceinline__ float tanh_fast(float x) {
    float a = fabsf(x);
    float e = __expf(-2.f * a);
    float t = __fdividef(1.f - e, 1.f + e);
    return (x < 0.f) ? -t : t;
}
__device__ __forceinline__ float neg_inf() { return __int_as_float(0xff800000); }

// ================= prolog GEMM: C[M,N] = A[M,K] @ W[N,K]^T + bias ==========
struct ACtx {  // row r = (b*L + l)  ->  context[l, b, :]
    const float* c;
    __device__ __forceinline__ float ld_(int r, int k) const {
        int b = r / LL; int l = r - b * LL;
        return c[((size_t)l * BB + b) * HH + k];
    }
};
struct WDirect {
    const float* w; int ld;
    __device__ __forceinline__ float ld_(int n, int k) const { return w[(size_t)n * ld + k]; }
};

template<int BM, int BN, int BK, int TM, int TN, class AT, class WT>
__global__ void gemm_kernel(AT A, WT W, const float* bias1,
                            float* C, int M, int N, int K) {
    constexpr int THREADS = (BM / TM) * (BN / TN);
    constexpr int ASTR = BM + TM;
    constexpr int WSTR = BN + TN;
    constexpr int LA = BM * BK / THREADS;
    constexpr int LW = BN * BK / THREADS;
    __shared__ __align__(16) float As[2][BK * ASTR];
    __shared__ __align__(16) float Ws[2][BK * WSTR];

    int tid = threadIdx.x;
    int m0 = blockIdx.x * BM;
    int n0 = blockIdx.y * BN;
    int tn = tid % (BN / TN);
    int tm = tid / (BN / TN);
    int rm = tm * TM, rn = tn * TN;

    float acc[TM][TN] = {};
    float ra[LA], rw[LW];
    const int nt = K / BK;

#pragma unroll
    for (int i = 0; i < LA; i++) { int e = tid + i * THREADS; ra[i] = A.ld_(m0 + e / BK, e % BK); }
#pragma unroll
    for (int i = 0; i < LW; i++) { int e = tid + i * THREADS; rw[i] = W.ld_(n0 + e / BK, e % BK); }
#pragma unroll
    for (int i = 0; i < LA; i++) { int e = tid + i * THREADS; As[0][(e % BK) * ASTR + e / BK] = ra[i]; }
#pragma unroll
    for (int i = 0; i < LW; i++) { int e = tid + i * THREADS; Ws[0][(e % BK) * WSTR + e / BK] = rw[i]; }
    __syncthreads();

    int cur = 0;
    for (int t = 0; t < nt; t++) {
        int k0n = (t + 1) * BK;
        if (t + 1 < nt) {
#pragma unroll
            for (int i = 0; i < LA; i++) { int e = tid + i * THREADS; ra[i] = A.ld_(m0 + e / BK, k0n + e % BK); }
#pragma unroll
            for (int i = 0; i < LW; i++) { int e = tid + i * THREADS; rw[i] = W.ld_(n0 + e / BK, k0n + e % BK); }
        }
#pragma unroll
        for (int k = 0; k < BK; k++) {
            float fa[TM], fb[TN];
#pragma unroll
            for (int v = 0; v < TM; v += 4) {
                float4 t4 = *reinterpret_cast<const float4*>(&As[cur][k * ASTR + rm + v]);
                fa[v] = t4.x; fa[v + 1] = t4.y; fa[v + 2] = t4.z; fa[v + 3] = t4.w;
            }
#pragma unroll
            for (int v = 0; v < TN; v += 4) {
                float4 t4 = *reinterpret_cast<const float4*>(&Ws[cur][k * WSTR + rn + v]);
                fb[v] = t4.x; fb[v + 1] = t4.y; fb[v + 2] = t4.z; fb[v + 3] = t4.w;
            }
#pragma unroll
            for (int i = 0; i < TM; i++)
#pragma unroll
                for (int j = 0; j < TN; j++)
                    acc[i][j] += fa[i] * fb[j];
        }
        if (t + 1 < nt) {
#pragma unroll
            for (int i = 0; i < LA; i++) { int e = tid + i * THREADS; As[cur ^ 1][(e % BK) * ASTR + e / BK] = ra[i]; }
#pragma unroll
            for (int i = 0; i < LW; i++) { int e = tid + i * THREADS; Ws[cur ^ 1][(e % BK) * WSTR + e / BK] = rw[i]; }
        }
        __syncthreads();
        cur ^= 1;
    }

#pragma unroll
    for (int j = 0; j < TN; j++) {
        int n = n0 + rn + j;
        float bsum = bias1 ? bias1[n] : 0.f;
#pragma unroll
        for (int i = 0; i < TM; i++) {
            int m = m0 + rm + i;
            C[(size_t)m * N + n] = acc[i][j] + bsum;
        }
    }
}

// ---------------- prolog: permute gate weights k-major + bias sums ----------------
__global__ void prep_kernel(const float* __restrict__ Wi, const float* __restrict__ Wh,
                            const float* __restrict__ bi, const float* __restrict__ bh) {
    int i = blockIdx.x * 256 + threadIdx.x;
    if (i < 512 * 1024) {
        int k = i >> 10, n = i & 1023;
        int g = n & 3, h = n >> 2;
        int row = g * HH + h;
        d_wperm[i] = (k < EE) ? Wi[row * EE + k] : Wh[row * HH + (k - EE)];
    }
    if (i < 1024) {
        int g = i & 3, h = i >> 2;
        d_bsum[i] = bi[g * HH + h] + bh[g * HH + h];
    }
}

// ============ PERSISTENT kernel: full 100-step recurrence, 4 rows/block ============
// Gates: per-output single-accumulator FFMA chain, k ascending 0..511 — bitwise
// identical to the round-13 tiled GEMM. Attention phase transcribed verbatim
// from round 13 (incl. stride-2 two-accumulator readout).
__global__ __launch_bounds__(1024, 1)
void decode_persist(const float* __restrict__ dec, const float* __restrict__ h0,
                    const float* __restrict__ c0,
                    const float* __restrict__ gWq, const float* __restrict__ gbq,
                    const float* __restrict__ gv,
                    const float* __restrict__ pWq, const float* __restrict__ pbq,
                    const float* __restrict__ pv,
                    const float* __restrict__ emb,
                    float* __restrict__ out) {
    extern __shared__ char smem_raw[];
    float4* WsT = (float4*)smem_raw;                       // 2 * 8*257 float4 = 65792 B
    float* hq  = (float*)(smem_raw + 65792);               // [4][256] h then g
    float* qs  = hq + 1024;                                 // [4][256]
    float* vs  = qs + 1024;                                 // [256]
    float* xs  = vs + 256;                                  // [4][256]
    float* hs  = xs + 1024;                                 // [4][256]
    float* cs  = hs + 1024;                                 // [4][256]
    float* lg  = cs + 1024;                                 // [4][100]
    float* wsb = lg + 4 * LL;                                // [4][100]
    int* sidx  = (int*)(wsb + 4 * LL);                       // [4]
    int* prevP = sidx + 4;                                   // [4]
    unsigned char* msS = (unsigned char*)(prevP + 4);        // [4][100]

    int tid = threadIdx.x;
    int warp = tid >> 5, lane = tid & 31;
    int b0 = blockIdx.x * 4;

    // ---- init persistent state
    {
        int r = tid >> 8, cc = tid & 255;
        xs[tid] = dec[(size_t)(b0 + r) * EE + cc];
        hs[tid] = h0[(size_t)(b0 + r) * HH + cc];
        cs[tid] = c0[(size_t)(b0 + r) * HH + cc];
    }
    if (tid < 4 * LL) msS[tid] = 0;
    if (tid < 4) prevP[tid] = 0;
    __syncthreads();

    const float4* Wp4 = (const float4*)d_wperm;
    float* out_probs = out;                               // T*B*L
    float* out_sel   = out + (size_t)TT * BB * LL;        // T*B

    for (int step = 0; step < TT; step++) {
        // ================= gates GEMM + LSTM (phase 1) =================
        float4 acc0 = {0, 0, 0, 0}, acc1 = {0, 0, 0, 0},
               acc2 = {0, 0, 0, 0}, acc3 = {0, 0, 0, 0};
        {   // prologue: tile 0 into buf 0
            float4 r0 = Wp4[tid];
            float4 r1 = Wp4[tid + 1024];
            WsT[(tid >> 8) * 257 + (tid & 255)] = r0;
            WsT[((tid + 1024) >> 8) * 257 + (tid & 255)] = r1;
        }
        __syncthreads();
        int buf = 0;
        for (int t = 0; t < 64; t++) {
            float4 r0, r1;
            if (t + 1 < 64) {
                r0 = Wp4[(size_t)(t + 1) * 2048 + tid];
                r1 = Wp4[(size_t)(t + 1) * 2048 + tid + 1024];
            }
            if (tid < 256) {
                int k0 = t * 8;
                const float* ab = (k0 < EE) ? (xs + k0) : (hs + (k0 - EE));
                const float4* wrow = WsT + buf * 2056 + tid;
#pragma unroll
                for (int kk = 0; kk < 8; kk++) {
                    float4 w = wrow[kk * 257];
                    float a0 = ab[kk];
                    float a1 = ab[256 + kk];
                    float a2 = ab[512 + kk];
                    float a3 = ab[768 + kk];
                    acc0.x += a0 * w.x; acc0.y += a0 * w.y; acc0.z += a0 * w.z; acc0.w += a0 * w.w;
                    acc1.x += a1 * w.x; acc1.y += a1 * w.y; acc1.z += a1 * w.z; acc1.w += a1 * w.w;
                    acc2.x += a2 * w.x; acc2.y += a2 * w.y; acc2.z += a2 * w.z; acc2.w += a2 * w.w;
                    acc3.x += a3 * w.x; acc3.y += a3 * w.y; acc3.z += a3 * w.z; acc3.w += a3 * w.w;
                }
            }
            if (t + 1 < 64) {
                int nb = buf ^ 1;
                WsT[nb * 2056 + (tid >> 8) * 257 + (tid & 255)] = r0;
                WsT[nb * 2056 + ((tid + 1024) >> 8) * 257 + (tid & 255)] = r1;
            }
            __syncthreads();
            buf ^= 1;
        }
        // LSTM epilogue (thread tid<256 owns h-column tid for all 4 rows)
        if (tid < 256) {
            float4 bs = ((const float4*)d_bsum)[tid];
            {
                float ig = acc0.x + bs.x, fg = acc0.y + bs.y, cg = acc0.z + bs.z, og = acc0.w + bs.w;
                float cy = sigf(fg) * cs[0 * 256 + tid] + sigf(ig) * tanh_fast(cg);
                float hy = sigf(og) * tanh_fast(cy);
                cs[0 * 256 + tid] = cy; hs[0 * 256 + tid] = hy; hq[0 * 256 + tid] = hy;
            }
            {
                float ig = acc1.x + bs.x, fg = acc1.y + bs.y, cg = acc1.z + bs.z, og = acc1.w + bs.w;
                float cy = sigf(fg) * cs[1 * 256 + tid] + sigf(ig) * tanh_fast(cg);
                float hy = sigf(og) * tanh_fast(cy);
                cs[1 * 256 + tid] = cy; hs[1 * 256 + tid] = hy; hq[1 * 256 + tid] = hy;
            }
            {
                float ig = acc2.x + bs.x, fg = acc2.y + bs.y, cg = acc2.z + bs.z, og = acc2.w + bs.w;
                float cy = sigf(fg) * cs[2 * 256 + tid] + sigf(ig) * tanh_fast(cg);
                float hy = sigf(og) * tanh_fast(cy);
                cs[2 * 256 + tid] = cy; hs[2 * 256 + tid] = hy; hq[2 * 256 + tid] = hy;
            }
            {
                float ig = acc3.x + bs.x, fg = acc3.y + bs.y, cg = acc3.z + bs.z, og = acc3.w + bs.w;
                float cy = sigf(fg) * cs[3 * 256 + tid] + sigf(ig) * tanh_fast(cg);
                float hy = sigf(og) * tanh_fast(cy);
                cs[3 * 256 + tid] = cy; hs[3 * 256 + tid] = hy; hq[3 * 256 + tid] = hy;
            }
        }
        __syncthreads();

        // ================= attention (phase 2, verbatim round-13 math) =================
        if (tid < HH) vs[tid] = gv[tid];
        if (tid < 4) {
            if (step == 0) msS[tid * LL + 0] = 1;
            else { if (step == 1) msS[tid * LL + 0] = 0; msS[tid * LL + prevP[tid]] = 1; }
        }
        __syncthreads();

        const float4* h0_4 = reinterpret_cast<const float4*>(hq);
        const float4* h1_4 = reinterpret_cast<const float4*>(hq + 256);
        const float4* h2_4 = reinterpret_cast<const float4*>(hq + 512);
        const float4* h3_4 = reinterpret_cast<const float4*>(hq + 768);

        // ---- qp = h @ gWq^T + gbq
        {
            const float4* W4 = reinterpret_cast<const float4*>(gWq);
            float4 a0 = h0_4[lane], a1 = h0_4[lane + 32];
            float4 b0v = h1_4[lane], b1v = h1_4[lane + 32];
            float4 c0v = h2_4[lane], c1v = h2_4[lane + 32];
            float4 d0v = h3_4[lane], d1v = h3_4[lane + 32];
#pragma unroll
            for (int r = 0; r < 8; r++) {
                int o = warp * 8 + r;
                float4 w0 = W4[(size_t)o * 64 + lane];
                float4 w1 = W4[(size_t)o * 64 + 32 + lane];
                float A = w0.x * a0.x + w0.y * a0.y + w0.z * a0.z + w0.w * a0.w
                        + w1.x * a1.x + w1.y * a1.y + w1.z * a1.z + w1.w * a1.w;
                float B = w0.x * b0v.x + w0.y * b0v.y + w0.z * b0v.z + w0.w * b0v.w
                        + w1.x * b1v.x + w1.y * b1v.y + w1.z * b1v.z + w1.w * b1v.w;
                float C = w0.x * c0v.x + w0.y * c0v.y + w0.z * c0v.z + w0.w * c0v.w
                        + w1.x * c1v.x + w1.y * c1v.y + w1.z * c1v.z + w1.w * c1v.w;
                float D = w0.x * d0v.x + w0.y * d0v.y + w0.z * d0v.z + w0.w * d0v.w
                        + w1.x * d1v.x + w1.y * d1v.y + w1.z * d1v.z + w1.w * d1v.w;
#pragma unroll
                for (int off = 16; off; off >>= 1) {
                    A += __shfl_xor_sync(0xffffffffu, A, off);
                    B += __shfl_xor_sync(0xffffffffu, B, off);
                    C += __shfl_xor_sync(0xffffffffu, C, off);
                    D += __shfl_xor_sync(0xffffffffu, D, off);
                }
                if (lane == 0) {
                    float bq = gbq[o];
                    qs[0 * 256 + o] = A + bq; qs[1 * 256 + o] = B + bq;
                    qs[2 * 256 + o] = C + bq; qs[3 * 256 + o] = D + bq;
                }
            }
        }
        __syncthreads();

        // ---- glimpse logits
        {
            int bl = warp >> 3, sub = warp & 7;
            const float4* qb = reinterpret_cast<const float4*>(qs + bl * 256);
            const float4* vb = reinterpret_cast<const float4*>(vs);
            float4 q0 = qb[lane], q1 = qb[lane + 32];
            float4 v0 = vb[lane], v1 = vb[lane + 32];
            const float4* eb4 = reinterpret_cast<const float4*>(d_eg + (size_t)(b0 + bl) * LL * HH);
            for (int l = sub; l < LL; l += 8) {
                float4 e0 = eb4[(size_t)l * 64 + lane];
                float4 e1 = eb4[(size_t)l * 64 + 32 + lane];
                float acc = v0.x * tanh_fast(q0.x + e0.x) + v0.y * tanh_fast(q0.y + e0.y)
                          + v0.z * tanh_fast(q0.z + e0.z) + v0.w * tanh_fast(q0.w + e0.w)
                          + v1.x * tanh_fast(q1.x + e1.x) + v1.y * tanh_fast(q1.y + e1.y)
                          + v1.z * tanh_fast(q1.z + e1.z) + v1.w * tanh_fast(q1.w + e1.w);
#pragma unroll
                for (int o = 16; o; o >>= 1) acc += __shfl_xor_sync(0xffffffffu, acc, o);
                if (lane == 0) lg[bl * LL + l] = msS[bl * LL + l] ? neg_inf() : acc;
            }
        }
        __syncthreads();

        // ---- glimpse softmax
        if (warp < 4) {
            int bl = warp;
            float v[4]; float mx = neg_inf();
#pragma unroll
            for (int i = 0; i < 4; i++) {
                int l = lane + i * 32;
                v[i] = (l < LL) ? lg[bl * LL + l] : neg_inf();
                mx = fmaxf(mx, v[i]);
            }
#pragma unroll
            for (int o = 16; o; o >>= 1) mx = fmaxf(mx, __shfl_xor_sync(0xffffffffu, mx, o));
            float s = 0.f;
#pragma unroll
            for (int i = 0; i < 4; i++) { v[i] = __expf(v[i] - mx); s += v[i]; }
#pragma unroll
            for (int o = 16; o; o >>= 1) s += __shfl_xor_sync(0xffffffffu, s, o);
            float inv = __fdividef(1.f, s);
#pragma unroll
            for (int i = 0; i < 4; i++) {
                int l = lane + i * 32;
                if (l < LL) wsb[bl * LL + l] = v[i] * inv;
            }
        }
        __syncthreads();

        // ---- readout (EXACT stride-2 two-accumulator order)
        {
            int bl = tid >> 8, h = tid & 255;
            const float* eb = d_eg + (size_t)(b0 + bl) * LL * HH + h;
            float g0 = 0.f, g1 = 0.f;
#pragma unroll 2
            for (int l = 0; l < LL; l += 2) {
                g0 += wsb[bl * LL + l] * eb[(size_t)l * HH];
                g1 += wsb[bl * LL + l + 1] * eb[(size_t)(l + 1) * HH];
            }
            hq[bl * 256 + h] = g0 + g1;  // overwrite h with g
            if (tid < HH) vs[tid] = pv[tid];
        }
        __syncthreads();

        // ---- qpp = g @ pWq^T + pbq
        {
            const float4* W4 = reinterpret_cast<const float4*>(pWq);
            float4 a0 = h0_4[lane], a1 = h0_4[lane + 32];
            float4 b0v = h1_4[lane], b1v = h1_4[lane + 32];
            float4 c0v = h2_4[lane], c1v = h2_4[lane + 32];
            float4 d0v = h3_4[lane], d1v = h3_4[lane + 32];
#pragma unroll
            for (int r = 0; r < 8; r++) {
                int o = warp * 8 + r;
                float4 w0 = W4[(size_t)o * 64 + lane];
                float4 w1 = W4[(size_t)o * 64 + 32 + lane];
                float A = w0.x * a0.x + w0.y * a0.y + w0.z * a0.z + w0.w * a0.w
                        + w1.x * a1.x + w1.y * a1.y + w1.z * a1.z + w1.w * a1.w;
                float B = w0.x * b0v.x + w0.y * b0v.y + w0.z * b0v.z + w0.w * b0v.w
                        + w1.x * b1v.x + w1.y * b1v.y + w1.z * b1v.z + w1.w * b1v.w;
                float C = w0.x * c0v.x + w0.y * c0v.y + w0.z * c0v.z + w0.w * c0v.w
                        + w1.x * c1v.x + w1.y * c1v.y + w1.z * c1v.z + w1.w * c1v.w;
                float D = w0.x * d0v.x + w0.y * d0v.y + w0.z * d0v.z + w0.w * d0v.w
                        + w1.x * d1v.x + w1.y * d1v.y + w1.z * d1v.z + w1.w * d1v.w;
#pragma unroll
                for (int off = 16; off; off >>= 1) {
                    A += __shfl_xor_sync(0xffffffffu, A, off);
                    B += __shfl_xor_sync(0xffffffffu, B, off);
                    C += __shfl_xor_sync(0xffffffffu, C, off);
                    D += __shfl_xor_sync(0xffffffffu, D, off);
                }
                if (lane == 0) {
                    float bq = pbq[o];
                    qs[0 * 256 + o] = A + bq; qs[1 * 256 + o] = B + bq;
                    qs[2 * 256 + o] = C + bq; qs[3 * 256 + o] = D + bq;
                }
            }
        }
        __syncthreads();

        // ---- pointer logits
        {
            int bl = warp >> 3, sub = warp & 7;
            const float4* qb = reinterpret_cast<const float4*>(qs + bl * 256);
            const float4* vb = reinterpret_cast<const float4*>(vs);
            float4 q0 = qb[lane], q1 = qb[lane + 32];
            float4 v0 = vb[lane], v1 = vb[lane + 32];
            const float4* eb4 = reinterpret_cast<const float4*>(d_ep + (size_t)(b0 + bl) * LL * HH);
            for (int l = sub; l < LL; l += 8) {
                float4 e0 = eb4[(size_t)l * 64 + lane];
                float4 e1 = eb4[(size_t)l * 64 + 32 + lane];
                float acc = v0.x * tanh_fast(q0.x + e0.x) + v0.y * tanh_fast(q0.y + e0.y)
                          + v0.z * tanh_fast(q0.z + e0.z) + v0.w * tanh_fast(q0.w + e0.w)
                          + v1.x * tanh_fast(q1.x + e1.x) + v1.y * tanh_fast(q1.y + e1.y)
                          + v1.z * tanh_fast(q1.z + e1.z) + v1.w * tanh_fast(q1.w + e1.w);
#pragma unroll
                for (int o = 16; o; o >>= 1) acc += __shfl_xor_sync(0xffffffffu, acc, o);
                if (lane == 0) lg[bl * LL + l] = msS[bl * LL + l] ? neg_inf() : (10.0f * tanh_fast(acc));
            }
        }
        __syncthreads();

        // ---- pointer softmax + argmax (jnp first-occurrence tie-break)
        if (warp < 4) {
            int bl = warp;
            float v[4]; float mx = neg_inf();
#pragma unroll
            for (int i = 0; i < 4; i++) {
                int l = lane + i * 32;
                v[i] = (l < LL) ? lg[bl * LL + l] : neg_inf();
                mx = fmaxf(mx, v[i]);
            }
#pragma unroll
            for (int o = 16; o; o >>= 1) mx = fmaxf(mx, __shfl_xor_sync(0xffffffffu, mx, o));
            float s = 0.f;
#pragma unroll
            for (int i = 0; i < 4; i++) { v[i] = __expf(v[i] - mx); s += v[i]; }
#pragma unroll
            for (int o = 16; o; o >>= 1) s += __shfl_xor_sync(0xffffffffu, s, o);
            float inv = __fdividef(1.f, s);
            float bv = -1.f; int bi_ = 0;
#pragma unroll
            for (int i = 0; i < 4; i++) {
                int l = lane + i * 32;
                if (l < LL) {
                    float p = v[i] * inv;
                    wsb[bl * LL + l] = p;
                    if (p > bv) { bv = p; bi_ = l; }
                }
            }
#pragma unroll
            for (int o = 16; o; o >>= 1) {
                float ov = __shfl_xor_sync(0xffffffffu, bv, o);
                int oi = __shfl_xor_sync(0xffffffffu, bi_, o);
                if (ov > bv || (ov == bv && oi < bi_)) { bv = ov; bi_ = oi; }
            }
            if (lane == 0) {
                sidx[bl] = bi_;
                prevP[bl] = bi_;
                out_sel[(size_t)step * BB + b0 + bl] = (float)bi_;
            }
        }
        __syncthreads();

        // ---- outputs + next x
        if (tid < 4 * LL) {
            int bl = tid / LL, l = tid % LL;
            out_probs[((size_t)step * BB + b0 + bl) * LL + l] = wsb[bl * LL + l];
        }
        {
            int bl = tid >> 8, h = tid & 255;
            xs[bl * 256 + h] = emb[((size_t)sidx[bl] * BB + (b0 + bl)) * EE + h];
        }
        __syncthreads();
    }

    // ---- final h, c tails
    {
        int r = tid >> 8, cc = tid & 255;
        size_t base = (size_t)TT * BB * LL + (size_t)TT * BB;
        out[base + (size_t)(b0 + r) * HH + cc] = hs[tid];
        out[base + (size_t)BB * HH + (size_t)(b0 + r) * HH + cc] = cs[tid];
    }
}

#define PERSIST_SMEM 90928

// ---------------- launch ----------------
extern "C" void kernel_launch(void* const* d_in, const int* in_sizes, int n_in,
                              void* d_out, int out_size) {
    (void)out_size;

    float *p_eg, *p_ep;
    cudaGetSymbolAddress((void**)&p_eg, d_eg);
    cudaGetSymbolAddress((void**)&p_ep, d_ep);

    static const int sig_dict[19] = {131072, 13107200, 131072, 131072, 13107200,
                                     262144, 1024, 262144, 1024, 65536, 256,
                                     65536, 256, 256, 65536, 256, 65536, 256, 256};
    static const int alpha_map[19] = {6, 7, 13, 4, 5, 1, 3, 0, 2, 8, 10, 9, 11, 12, 14, 16, 15, 17, 18};
    bool dict_ok = (n_in == 19);
    if (dict_ok) for (int i = 0; i < 19; i++) if (in_sizes[i] != sig_dict[i]) { dict_ok = false; break; }
    const float* in[19];
    for (int i = 0; i < 19; i++)
        in[i] = (const float*)d_in[dict_ok ? i : alpha_map[i]];

    const float* dec   = in[0];
    const float* emb   = in[1];
    const float* h0    = in[2];
    const float* c0    = in[3];
    const float* ctx   = in[4];
    const float* Wi    = in[5];
    const float* bi    = in[6];
    const float* Wh    = in[7];
    const float* bh    = in[8];
    const float* gWq   = in[9];
    const float* gbq   = in[10];
    const float* gWref = in[11];
    const float* gbref = in[12];
    const float* gv    = in[13];
    const float* pWq   = in[14];
    const float* pbq   = in[15];
    const float* pWref = in[16];
    const float* pbref = in[17];
    const float* pv    = in[18];

    float* out = (float*)d_out;

    cudaFuncSetAttribute(decode_persist,
                         cudaFuncAttributeMaxDynamicSharedMemorySize, PERSIST_SMEM);

    // prolog: weight permute + bias sums
    prep_kernel<<<(512 * 1024 + 255) / 256, 256>>>(Wi, Wh, bi, bh);

    // prolog: e_g / e_p  (M=51200, N=256, K=256)
    {
        ACtx a{ctx};
        WDirect wg{gWref, HH};
        gemm_kernel<128, 128, 8, 8, 8><<<dim3(BB * LL / 128, HH / 128), 256>>>(
            a, wg, gbref, p_eg, BB * LL, HH, HH);
        WDirect wp{pWref, HH};
        gemm_kernel<128, 128, 8, 8, 8><<<dim3(BB * LL / 128, HH / 128), 256>>>(
            a, wp, pbref, p_ep, BB * LL, HH, HH);
    }

    // the whole 100-step recurrence in ONE persistent kernel
    decode_persist<<<BB / 4, 1024, PERSIST_SMEM>>>(
        dec, h0, c0, gWq, gbq, gv, pWq, pbq, pv, emb, out);
}

// round 16
// speedup vs baseline: 1.1706x; 1.1706x over previous
#include <cuda_runtime.h>
#include <math.h>
#include <stddef.h>

#define BB 512
#define LL 100
#define EE 256
#define HH 256
#define TT 100
#define NG 1024  // 4*H

// ---------------- device scratch (no allocations allowed) ----------------
__device__ float d_eg[(size_t)BB * LL * HH];   // [b][l][h]  52.4 MB
__device__ float d_ep[(size_t)BB * LL * HH];   // [b][l][h]  52.4 MB
__device__ float d_x[BB * EE];
__device__ float d_h0b[BB * HH];
__device__ float d_h1b[BB * HH];
__device__ float d_c0b[BB * HH];
__device__ float d_c1b[BB * HH];
__device__ unsigned char d_mask[BB * LL];
__device__ int d_prev[BB];

__device__ __forceinline__ float sigf(float x) { return __fdividef(1.f, 1.f + __expf(-x)); }
__device__ __forceinline__ float tanh_fast(float x) {
    float a = fabsf(x);
    float e = __expf(-2.f * a);
    float t = __fdividef(1.f - e, 1.f + e);
    return (x < 0.f) ? -t : t;
}
__device__ __forceinline__ float neg_inf() { return __int_as_float(0xff800000); }

// ================= generic GEMM: C[M,N] = A[M,K] @ W[N,K]^T + bias ==========
struct ACtx {  // row r = (b*L + l)  ->  context[l, b, :]
    const float* c;
    __device__ __forceinline__ float ld_(int r, int k) const {
        int b = r / LL; int l = r - b * LL;
        return c[((size_t)l * BB + b) * HH + k];
    }
};
struct WDirect {
    const float* w; int ld;
    __device__ __forceinline__ float ld_(int n, int k) const { return w[(size_t)n * ld + k]; }
};

template<int BM, int BN, int BK, int TM, int TN, class AT, class WT>
__global__ void gemm_kernel(AT A, WT W, const float* bias1,
                            float* C, int M, int N, int K) {
    constexpr int THREADS = (BM / TM) * (BN / TN);
    constexpr int ASTR = BM + TM;
    constexpr int WSTR = BN + TN;
    constexpr int LA = BM * BK / THREADS;
    constexpr int LW = BN * BK / THREADS;
    __shared__ __align__(16) float As[2][BK * ASTR];
    __shared__ __align__(16) float Ws[2][BK * WSTR];

    int tid = threadIdx.x;
    int m0 = blockIdx.x * BM;
    int n0 = blockIdx.y * BN;
    int tn = tid % (BN / TN);
    int tm = tid / (BN / TN);
    int rm = tm * TM, rn = tn * TN;

    float acc[TM][TN] = {};
    float ra[LA], rw[LW];
    const int nt = K / BK;

#pragma unroll
    for (int i = 0; i < LA; i++) { int e = tid + i * THREADS; ra[i] = A.ld_(m0 + e / BK, e % BK); }
#pragma unroll
    for (int i = 0; i < LW; i++) { int e = tid + i * THREADS; rw[i] = W.ld_(n0 + e / BK, e % BK); }
#pragma unroll
    for (int i = 0; i < LA; i++) { int e = tid + i * THREADS; As[0][(e % BK) * ASTR + e / BK] = ra[i]; }
#pragma unroll
    for (int i = 0; i < LW; i++) { int e = tid + i * THREADS; Ws[0][(e % BK) * WSTR + e / BK] = rw[i]; }
    __syncthreads();

    int cur = 0;
    for (int t = 0; t < nt; t++) {
        int k0n = (t + 1) * BK;
        if (t + 1 < nt) {
#pragma unroll
            for (int i = 0; i < LA; i++) { int e = tid + i * THREADS; ra[i] = A.ld_(m0 + e / BK, k0n + e % BK); }
#pragma unroll
            for (int i = 0; i < LW; i++) { int e = tid + i * THREADS; rw[i] = W.ld_(n0 + e / BK, k0n + e % BK); }
        }
#pragma unroll
        for (int k = 0; k < BK; k++) {
            float fa[TM], fb[TN];
#pragma unroll
            for (int v = 0; v < TM; v += 4) {
                float4 t4 = *reinterpret_cast<const float4*>(&As[cur][k * ASTR + rm + v]);
                fa[v] = t4.x; fa[v + 1] = t4.y; fa[v + 2] = t4.z; fa[v + 3] = t4.w;
            }
#pragma unroll
            for (int v = 0; v < TN; v += 4) {
                float4 t4 = *reinterpret_cast<const float4*>(&Ws[cur][k * WSTR + rn + v]);
                fb[v] = t4.x; fb[v + 1] = t4.y; fb[v + 2] = t4.z; fb[v + 3] = t4.w;
            }
#pragma unroll
            for (int i = 0; i < TM; i++)
#pragma unroll
                for (int j = 0; j < TN; j++)
                    acc[i][j] += fa[i] * fb[j];
        }
        if (t + 1 < nt) {
#pragma unroll
            for (int i = 0; i < LA; i++) { int e = tid + i * THREADS; As[cur ^ 1][(e % BK) * ASTR + e / BK] = ra[i]; }
#pragma unroll
            for (int i = 0; i < LW; i++) { int e = tid + i * THREADS; Ws[cur ^ 1][(e % BK) * WSTR + e / BK] = rw[i]; }
        }
        __syncthreads();
        cur ^= 1;
    }

#pragma unroll
    for (int j = 0; j < TN; j++) {
        int n = n0 + rn + j;
        float bsum = bias1 ? bias1[n] : 0.f;
#pragma unroll
        for (int i = 0; i < TM; i++) {
            int m = m0 + rm + i;
            C[(size_t)m * N + n] = acc[i][j] + bsum;
        }
    }
}

// ============ fused gates GEMM + LSTM epilogue ============
// Columns interleaved n = 4h+g (g=0..3 = i,f,c,o): each thread's TN=4 columns
// are the 4 gates of one h. Per-output single-accumulator FFMA chain, k ascending
// — bitwise identical to rounds 11/13.
// NEW SCHEDULE: BM=32, BN=128, BK=16, TM=4, TN=4 -> 256 threads (8 warps,
// 2 warps/SMSP for latency hiding), grid (16,8)=128 blocks, single wave.
__global__ __launch_bounds__(256)
void gates_lstm_kernel(const float* __restrict__ x,
                       const float* __restrict__ h_in,
                       const float* __restrict__ Wi,
                       const float* __restrict__ Wh,
                       const float* __restrict__ bi,
                       const float* __restrict__ bh,
                       const float* __restrict__ c_in,
                       float* __restrict__ c_out,
                       float* __restrict__ h_out) {
    constexpr int BM = 32, BN = 128, BK = 16, TM = 4, TN = 4, THREADS = 256;
    constexpr int ASTR = BM + 4, WSTR = BN + 4;
    constexpr int KK = EE + HH;            // 512
    constexpr int LA = BM * BK / THREADS;  // 2
    constexpr int LW = BN * BK / THREADS;  // 8
    __shared__ __align__(16) float As[2][BK * ASTR];
    __shared__ __align__(16) float Ws[2][BK * WSTR];

    int tid = threadIdx.x;
    int m0 = blockIdx.x * BM;
    int n0 = blockIdx.y * BN;
    int tn = tid % (BN / TN);   // 32 (== lane -> consecutive W float4)
    int tm = tid / (BN / TN);   // 8  (uniform per warp -> A broadcast)
    int rm = tm * TM, rn = tn * TN;

    auto ldA = [&](int r, int k) -> float {
        return (k < EE) ? x[r * EE + k] : h_in[r * HH + (k - EE)];
    };
    auto ldW = [&](int n, int k) -> float {
        int g = n & 3, h = n >> 2;
        int row = g * HH + h;
        return (k < EE) ? Wi[row * EE + k] : Wh[row * HH + (k - EE)];
    };

    float acc[TM][TN] = {};
    float ra[LA], rw[LW];
    const int nt = KK / BK;  // 32

#pragma unroll
    for (int i = 0; i < LA; i++) { int e = tid + i * THREADS; ra[i] = ldA(m0 + e / BK, e % BK); }
#pragma unroll
    for (int i = 0; i < LW; i++) { int e = tid + i * THREADS; rw[i] = ldW(n0 + e / BK, e % BK); }
#pragma unroll
    for (int i = 0; i < LA; i++) { int e = tid + i * THREADS; As[0][(e % BK) * ASTR + e / BK] = ra[i]; }
#pragma unroll
    for (int i = 0; i < LW; i++) { int e = tid + i * THREADS; Ws[0][(e % BK) * WSTR + e / BK] = rw[i]; }
    __syncthreads();

    int cur = 0;
    for (int t = 0; t < nt; t++) {
        int k0n = (t + 1) * BK;
        if (t + 1 < nt) {
#pragma unroll
            for (int i = 0; i < LA; i++) { int e = tid + i * THREADS; ra[i] = ldA(m0 + e / BK, k0n + e % BK); }
#pragma unroll
            for (int i = 0; i < LW; i++) { int e = tid + i * THREADS; rw[i] = ldW(n0 + e / BK, k0n + e % BK); }
        }
#pragma unroll
        for (int k = 0; k < BK; k++) {
            float4 a4 = *reinterpret_cast<const float4*>(&As[cur][k * ASTR + rm]);
            float4 w4 = *reinterpret_cast<const float4*>(&Ws[cur][k * WSTR + rn]);
            float fa[4] = {a4.x, a4.y, a4.z, a4.w};
            float fb[4] = {w4.x, w4.y, w4.z, w4.w};
#pragma unroll
            for (int i = 0; i < TM; i++)
#pragma unroll
                for (int j = 0; j < TN; j++)
                    acc[i][j] += fa[i] * fb[j];
        }
        if (t + 1 < nt) {
#pragma unroll
            for (int i = 0; i < LA; i++) { int e = tid + i * THREADS; As[cur ^ 1][(e % BK) * ASTR + e / BK] = ra[i]; }
#pragma unroll
            for (int i = 0; i < LW; i++) { int e = tid + i * THREADS; Ws[cur ^ 1][(e % BK) * WSTR + e / BK] = rw[i]; }
        }
        __syncthreads();
        cur ^= 1;
    }

    // LSTM epilogue: this thread's TN=4 columns are the 4 gates of one h
    int h = (n0 + rn) >> 2;
    float b0 = bi[0 * HH + h] + bh[0 * HH + h];
    float b1 = bi[1 * HH + h] + bh[1 * HH + h];
    float b2 = bi[2 * HH + h] + bh[2 * HH + h];
    float b3 = bi[3 * HH + h] + bh[3 * HH + h];
#pragma unroll
    for (int i = 0; i < TM; i++) {
        int m = m0 + rm + i;
        float ig = acc[i][0] + b0;
        float fg = acc[i][1] + b1;
        float cg = acc[i][2] + b2;
        float og = acc[i][3] + b3;
        float cy = sigf(fg) * c_in[m * HH + h] + sigf(ig) * tanh_fast(cg);
        c_out[m * HH + h] = cy;
        h_out[m * HH + h] = sigf(og) * tanh_fast(cy);
    }
}

// ---------------- init ----------------
__global__ void init_kernel(const float* dec, const float* h0, const float* c0) {
    int i = blockIdx.x * blockDim.x + threadIdx.x;
    if (i < BB * EE) d_x[i] = dec[i];
    if (i < BB * HH) { d_h0b[i] = h0[i]; d_c0b[i] = c0[i]; }
    if (i < BB * LL) d_mask[i] = 0;
    if (i < BB) d_prev[i] = 0;
}

// ============ attention megakernel: 4 batches/block, 1024 threads, 128 blocks ====
// VERBATIM round 13 (8.41 ms PASS) — do not touch.
__global__ __launch_bounds__(1024)
void attn_kernel(int step,
                 const float* __restrict__ hnew,
                 const float* __restrict__ gWq, const float* __restrict__ gbq,
                 const float* __restrict__ gv,
                 const float* __restrict__ pWq, const float* __restrict__ pbq,
                 const float* __restrict__ pv,
                 const float* __restrict__ emb,
                 float* __restrict__ out_probs,
                 float* __restrict__ out_sel,
                 float* __restrict__ x_out) {
    int tid = threadIdx.x;                 // 1024
    int warp = tid >> 5, lane = tid & 31;  // 32 warps
    int b0 = blockIdx.x * 4;               // batches b0..b0+3

    __shared__ __align__(16) float hq[4][HH];  // h, later g
    __shared__ __align__(16) float qs[4][HH];
    __shared__ __align__(16) float vs[HH];
    __shared__ float lg[4][LL], ws[4][LL];
    __shared__ unsigned char ms[4][LL];
    __shared__ int sidx[4];

    // ---- load h (4x256 = 1024), v, masks
    if (tid < HH) vs[tid] = gv[tid];
    hq[tid >> 8][tid & 255] = hnew[(size_t)b0 * HH + tid];
    if (tid < 4 * LL) { int bl = tid / LL, l = tid % LL; ms[bl][l] = d_mask[(b0 + bl) * LL + l]; }
    __syncthreads();
    if (tid < 4) {
        if (step == 0) ms[tid][0] = 1;
        else { if (step == 1) ms[tid][0] = 0; ms[tid][d_prev[b0 + tid]] = 1; }
    }
    __syncthreads();
    if (tid < 4 * LL) { int bl = tid / LL, l = tid % LL; d_mask[(b0 + bl) * LL + l] = ms[bl][l]; }

    const float4* h0_4 = reinterpret_cast<const float4*>(hq[0]);
    const float4* h1_4 = reinterpret_cast<const float4*>(hq[1]);
    const float4* h2_4 = reinterpret_cast<const float4*>(hq[2]);
    const float4* h3_4 = reinterpret_cast<const float4*>(hq[3]);

    // ---- qp = h @ gWq^T + gbq : warp w computes rows [8w, 8w+8), all 4 batches
    {
        const float4* W4 = reinterpret_cast<const float4*>(gWq);
        float4 a0 = h0_4[lane], a1 = h0_4[lane + 32];
        float4 b0v = h1_4[lane], b1v = h1_4[lane + 32];
        float4 c0v = h2_4[lane], c1v = h2_4[lane + 32];
        float4 d0v = h3_4[lane], d1v = h3_4[lane + 32];
#pragma unroll
        for (int r = 0; r < 8; r++) {
            int o = warp * 8 + r;
            float4 w0 = W4[(size_t)o * 64 + lane];
            float4 w1 = W4[(size_t)o * 64 + 32 + lane];
            float A = w0.x * a0.x + w0.y * a0.y + w0.z * a0.z + w0.w * a0.w
                    + w1.x * a1.x + w1.y * a1.y + w1.z * a1.z + w1.w * a1.w;
            float B = w0.x * b0v.x + w0.y * b0v.y + w0.z * b0v.z + w0.w * b0v.w
                    + w1.x * b1v.x + w1.y * b1v.y + w1.z * b1v.z + w1.w * b1v.w;
            float C = w0.x * c0v.x + w0.y * c0v.y + w0.z * c0v.z + w0.w * c0v.w
                    + w1.x * c1v.x + w1.y * c1v.y + w1.z * c1v.z + w1.w * c1v.w;
            float D = w0.x * d0v.x + w0.y * d0v.y + w0.z * d0v.z + w0.w * d0v.w
                    + w1.x * d1v.x + w1.y * d1v.y + w1.z * d1v.z + w1.w * d1v.w;
#pragma unroll
            for (int off = 16; off; off >>= 1) {
                A += __shfl_xor_sync(0xffffffffu, A, off);
                B += __shfl_xor_sync(0xffffffffu, B, off);
                C += __shfl_xor_sync(0xffffffffu, C, off);
                D += __shfl_xor_sync(0xffffffffu, D, off);
            }
            if (lane == 0) {
                float bq = gbq[o];
                qs[0][o] = A + bq; qs[1][o] = B + bq;
                qs[2][o] = C + bq; qs[3][o] = D + bq;
            }
        }
    }
    __syncthreads();

    // ---- glimpse logits: warp -> batch warp>>3, l strided by 8
    {
        int bl = warp >> 3, sub = warp & 7;
        const float4* qb = reinterpret_cast<const float4*>(qs[bl]);
        const float4* vb = reinterpret_cast<const float4*>(vs);
        float4 q0 = qb[lane], q1 = qb[lane + 32];
        float4 v0 = vb[lane], v1 = vb[lane + 32];
        const float4* eb4 = reinterpret_cast<const float4*>(d_eg + (size_t)(b0 + bl) * LL * HH);
        for (int l = sub; l < LL; l += 8) {
            float4 e0 = eb4[(size_t)l * 64 + lane];
            float4 e1 = eb4[(size_t)l * 64 + 32 + lane];
            float acc = v0.x * tanh_fast(q0.x + e0.x) + v0.y * tanh_fast(q0.y + e0.y)
                      + v0.z * tanh_fast(q0.z + e0.z) + v0.w * tanh_fast(q0.w + e0.w)
                      + v1.x * tanh_fast(q1.x + e1.x) + v1.y * tanh_fast(q1.y + e1.y)
                      + v1.z * tanh_fast(q1.z + e1.z) + v1.w * tanh_fast(q1.w + e1.w);
#pragma unroll
            for (int o = 16; o; o >>= 1) acc += __shfl_xor_sync(0xffffffffu, acc, o);
            if (lane == 0) lg[bl][l] = ms[bl][l] ? neg_inf() : acc;
        }
    }
    __syncthreads();

    // ---- glimpse softmax: warps 0..3, one per batch
    if (warp < 4) {
        int bl = warp;
        float v[4]; float mx = neg_inf();
#pragma unroll
        for (int i = 0; i < 4; i++) {
            int l = lane + i * 32;
            v[i] = (l < LL) ? lg[bl][l] : neg_inf();
            mx = fmaxf(mx, v[i]);
        }
#pragma unroll
        for (int o = 16; o; o >>= 1) mx = fmaxf(mx, __shfl_xor_sync(0xffffffffu, mx, o));
        float s = 0.f;
#pragma unroll
        for (int i = 0; i < 4; i++) { v[i] = __expf(v[i] - mx); s += v[i]; }
#pragma unroll
        for (int o = 16; o; o >>= 1) s += __shfl_xor_sync(0xffffffffu, s, o);
        float inv = __fdividef(1.f, s);
#pragma unroll
        for (int i = 0; i < 4; i++) {
            int l = lane + i * 32;
            if (l < LL) ws[bl][l] = v[i] * inv;
        }
    }
    __syncthreads();

    // ---- readout: EXACT stride-2 two-accumulator order
    {
        int bl = tid >> 8, h = tid & 255;
        const float* eb = d_eg + (size_t)(b0 + bl) * LL * HH + h;
        float g0 = 0.f, g1 = 0.f;
#pragma unroll 2
        for (int l = 0; l < LL; l += 2) {
            g0 += ws[bl][l] * eb[(size_t)l * HH];
            g1 += ws[bl][l + 1] * eb[(size_t)(l + 1) * HH];
        }
        hq[bl][h] = g0 + g1;  // overwrite h with g (h no longer needed)
        if (tid < HH) vs[tid] = pv[tid];
    }
    __syncthreads();

    // ---- qpp = g @ pWq^T + pbq
    {
        const float4* W4 = reinterpret_cast<const float4*>(pWq);
        float4 a0 = h0_4[lane], a1 = h0_4[lane + 32];
        float4 b0v = h1_4[lane], b1v = h1_4[lane + 32];
        float4 c0v = h2_4[lane], c1v = h2_4[lane + 32];
        float4 d0v = h3_4[lane], d1v = h3_4[lane + 32];
#pragma unroll
        for (int r = 0; r < 8; r++) {
            int o = warp * 8 + r;
            float4 w0 = W4[(size_t)o * 64 + lane];
            float4 w1 = W4[(size_t)o * 64 + 32 + lane];
            float A = w0.x * a0.x + w0.y * a0.y + w0.z * a0.z + w0.w * a0.w
                    + w1.x * a1.x + w1.y * a1.y + w1.z * a1.z + w1.w * a1.w;
            float B = w0.x * b0v.x + w0.y * b0v.y + w0.z * b0v.z + w0.w * b0v.w
                    + w1.x * b1v.x + w1.y * b1v.y + w1.z * b1v.z + w1.w * b1v.w;
            float C = w0.x * c0v.x + w0.y * c0v.y + w0.z * c0v.z + w0.w * c0v.w
                    + w1.x * c1v.x + w1.y * c1v.y + w1.z * c1v.z + w1.w * c1v.w;
            float D = w0.x * d0v.x + w0.y * d0v.y + w0.z * d0v.z + w0.w * d0v.w
                    + w1.x * d1v.x + w1.y * d1v.y + w1.z * d1v.z + w1.w * d1v.w;
#pragma unroll
            for (int off = 16; off; off >>= 1) {
                A += __shfl_xor_sync(0xffffffffu, A, off);
                B += __shfl_xor_sync(0xffffffffu, B, off);
                C += __shfl_xor_sync(0xffffffffu, C, off);
                D += __shfl_xor_sync(0xffffffffu, D, off);
            }
            if (lane == 0) {
                float bq = pbq[o];
                qs[0][o] = A + bq; qs[1][o] = B + bq;
                qs[2][o] = C + bq; qs[3][o] = D + bq;
            }
        }
    }
    __syncthreads();

    // ---- pointer logits
    {
        int bl = warp >> 3, sub = warp & 7;
        const float4* qb = reinterpret_cast<const float4*>(qs[bl]);
        const float4* vb = reinterpret_cast<const float4*>(vs);
        float4 q0 = qb[lane], q1 = qb[lane + 32];
        float4 v0 = vb[lane], v1 = vb[lane + 32];
        const float4* eb4 = reinterpret_cast<const float4*>(d_ep + (size_t)(b0 + bl) * LL * HH);
        for (int l = sub; l < LL; l += 8) {
            float4 e0 = eb4[(size_t)l * 64 + lane];
            float4 e1 = eb4[(size_t)l * 64 + 32 + lane];
            float acc = v0.x * tanh_fast(q0.x + e0.x) + v0.y * tanh_fast(q0.y + e0.y)
                      + v0.z * tanh_fast(q0.z + e0.z) + v0.w * tanh_fast(q0.w + e0.w)
                      + v1.x * tanh_fast(q1.x + e1.x) + v1.y * tanh_fast(q1.y + e1.y)
                      + v1.z * tanh_fast(q1.z + e1.z) + v1.w * tanh_fast(q1.w + e1.w);
#pragma unroll
            for (int o = 16; o; o >>= 1) acc += __shfl_xor_sync(0xffffffffu, acc, o);
            if (lane == 0) lg[bl][l] = ms[bl][l] ? neg_inf() : (10.0f * tanh_fast(acc));
        }
    }
    __syncthreads();

    // ---- pointer softmax + argmax (jnp first-occurrence tie-break)
    if (warp < 4) {
        int bl = warp;
        float v[4]; float mx = neg_inf();
#pragma unroll
        for (int i = 0; i < 4; i++) {
            int l = lane + i * 32;
            v[i] = (l < LL) ? lg[bl][l] : neg_inf();
            mx = fmaxf(mx, v[i]);
        }
#pragma unroll
        for (int o = 16; o; o >>= 1) mx = fmaxf(mx, __shfl_xor_sync(0xffffffffu, mx, o));
        float s = 0.f;
#pragma unroll
        for (int i = 0; i < 4; i++) { v[i] = __expf(v[i] - mx); s += v[i]; }
#pragma unroll
        for (int o = 16; o; o >>= 1) s += __shfl_xor_sync(0xffffffffu, s, o);
        float inv = __fdividef(1.f, s);
        float bv = -1.f; int bi_ = 0;
#pragma unroll
        for (int i = 0; i < 4; i++) {
            int l = lane + i * 32;
            if (l < LL) {
                float p = v[i] * inv;
                ws[bl][l] = p;
                if (p > bv) { bv = p; bi_ = l; }
            }
        }
#pragma unroll
        for (int o = 16; o; o >>= 1) {
            float ov = __shfl_xor_sync(0xffffffffu, bv, o);
            int oi = __shfl_xor_sync(0xffffffffu, bi_, o);
            if (ov > bv || (ov == bv && oi < bi_)) { bv = ov; bi_ = oi; }
        }
        if (lane == 0) {
            sidx[bl] = bi_;
            d_prev[b0 + bl] = bi_;
            out_sel[(size_t)step * BB + b0 + bl] = (float)bi_;
        }
    }
    __syncthreads();

    // ---- outputs
    if (tid < 4 * LL) {
        int bl = tid / LL, l = tid % LL;
        out_probs[((size_t)step * BB + b0 + bl) * LL + l] = ws[bl][l];
    }
    {
        int bl = tid >> 8, h = tid & 255;
        x_out[(size_t)(b0 + bl) * EE + h] = emb[((size_t)sidx[bl] * BB + (b0 + bl)) * EE + h];
    }
}

// ---------------- finalize: hx, cx tails ----------------
__global__ void finalize_kernel(const float* hfin, const float* cfin, float* out) {
    int i = blockIdx.x * 256 + threadIdx.x;
    if (i < BB * HH) {
        size_t base = (size_t)TT * BB * LL + (size_t)TT * BB;
        out[base + i] = hfin[i];
        out[base + (size_t)BB * HH + i] = cfin[i];
    }
}

// ---------------- launch ----------------
extern "C" void kernel_launch(void* const* d_in, const int* in_sizes, int n_in,
                              void* d_out, int out_size) {
    (void)out_size;

    float *p_eg, *p_ep, *p_x, *p_h0, *p_h1, *p_c0, *p_c1;
    cudaGetSymbolAddress((void**)&p_eg, d_eg);
    cudaGetSymbolAddress((void**)&p_ep, d_ep);
    cudaGetSymbolAddress((void**)&p_x, d_x);
    cudaGetSymbolAddress((void**)&p_h0, d_h0b);
    cudaGetSymbolAddress((void**)&p_h1, d_h1b);
    cudaGetSymbolAddress((void**)&p_c0, d_c0b);
    cudaGetSymbolAddress((void**)&p_c1, d_c1b);

    static const int sig_dict[19] = {131072, 13107200, 131072, 131072, 13107200,
                                     262144, 1024, 262144, 1024, 65536, 256,
                                     65536, 256, 256, 65536, 256, 65536, 256, 256};
    static const int alpha_map[19] = {6, 7, 13, 4, 5, 1, 3, 0, 2, 8, 10, 9, 11, 12, 14, 16, 15, 17, 18};
    bool dict_ok = (n_in == 19);
    if (dict_ok) for (int i = 0; i < 19; i++) if (in_sizes[i] != sig_dict[i]) { dict_ok = false; break; }
    const float* in[19];
    for (int i = 0; i < 19; i++)
        in[i] = (const float*)d_in[dict_ok ? i : alpha_map[i]];

    const float* dec   = in[0];
    const float* emb   = in[1];
    const float* h0    = in[2];
    const float* c0    = in[3];
    const float* ctx   = in[4];
    const float* Wi    = in[5];
    const float* bi    = in[6];
    const float* Wh    = in[7];
    const float* bh    = in[8];
    const float* gWq   = in[9];
    const float* gbq   = in[10];
    const float* gWref = in[11];
    const float* gbref = in[12];
    const float* gv    = in[13];
    const float* pWq   = in[14];
    const float* pbq   = in[15];
    const float* pWref = in[16];
    const float* pbref = in[17];
    const float* pv    = in[18];

    float* out = (float*)d_out;
    float* out_probs = out;                               // T*B*L
    float* out_sel   = out + (size_t)TT * BB * LL;        // T*B

    init_kernel<<<(BB * EE + 255) / 256, 256>>>(dec, h0, c0);

    // one-time: e_g / e_p  (M=51200, N=256, K=256)
    {
        ACtx a{ctx};
        WDirect wg{gWref, HH};
        gemm_kernel<128, 128, 8, 8, 8><<<dim3(BB * LL / 128, HH / 128), 256>>>(
            a, wg, gbref, p_eg, BB * LL, HH, HH);
        WDirect wp{pWref, HH};
        gemm_kernel<128, 128, 8, 8, 8><<<dim3(BB * LL / 128, HH / 128), 256>>>(
            a, wp, pbref, p_ep, BB * LL, HH, HH);
    }

    for (int t = 0; t < TT; t++) {
        const float* h_in = (t & 1) ? p_h1 : p_h0;
        const float* c_in = (t & 1) ? p_c1 : p_c0;
        float* h_out = (t & 1) ? p_h0 : p_h1;
        float* c_out = (t & 1) ? p_c0 : p_c1;

        gates_lstm_kernel<<<dim3(BB / 32, NG / 128), 256>>>(
            p_x, h_in, Wi, Wh, bi, bh, c_in, c_out, h_out);

        attn_kernel<<<BB / 4, 1024>>>(t, h_out, gWq, gbq, gv, pWq, pbq, pv,
                                      emb, out_probs, out_sel, p_x);
    }

    // t=99 (odd) wrote into buffer 0
    finalize_kernel<<<(BB * HH + 255) / 256, 256>>>(p_h0, p_c0, out);
}